// round 5
// baseline (speedup 1.0000x reference)
#include <cuda_runtime.h>
#include <cuda_bf16.h>

#define BB   4096
#define SS   128
#define DIN  64
#define DOUT 128
#define HH   32

// Fused first layer, transposed: g_WcT[j][d] = (W_net @ W1)[d][j]; bc = b_net@W1 + b1
__device__ float g_WcT[HH * DIN];
__device__ float g_bc[HH];

// ---------------------------------------------------------------------------
// Prologue: warp-per-element fold (32-way K split + butterfly), 260 x 8 warps.
// ---------------------------------------------------------------------------
__global__ __launch_bounds__(256) void prep_kernel(
        const float* __restrict__ Wnet, const float* __restrict__ bnet,
        const float* __restrict__ W1,   const float* __restrict__ b1) {
    const int warp = threadIdx.x >> 5;
    const int lane = threadIdx.x & 31;
    const int we   = blockIdx.x * 8 + warp;

    if (we < DIN * HH) {
        const int d = we >> 5, j = we & 31;
        const float4 wn = *reinterpret_cast<const float4*>(Wnet + d * DOUT + lane * 4);
        const int k = lane * 4;
        float acc = wn.x * W1[(k + 0) * HH + j];
        acc = fmaf(wn.y, W1[(k + 1) * HH + j], acc);
        acc = fmaf(wn.z, W1[(k + 2) * HH + j], acc);
        acc = fmaf(wn.w, W1[(k + 3) * HH + j], acc);
        #pragma unroll
        for (int off = 16; off; off >>= 1)
            acc += __shfl_xor_sync(0xffffffffu, acc, off);
        if (lane == 0) g_WcT[j * DIN + d] = acc;
    } else if (we < DIN * HH + HH) {
        const int j = we - DIN * HH;
        const int k = lane * 4;
        float acc = bnet[k + 0] * W1[(k + 0) * HH + j];
        acc = fmaf(bnet[k + 1], W1[(k + 1) * HH + j], acc);
        acc = fmaf(bnet[k + 2], W1[(k + 2) * HH + j], acc);
        acc = fmaf(bnet[k + 3], W1[(k + 3) * HH + j], acc);
        #pragma unroll
        for (int off = 16; off; off >>= 1)
            acc += __shfl_xor_sync(0xffffffffu, acc, off);
        if (lane == 0) g_bc[j] = b1[j] + acc;
    }
}

// ---------------------------------------------------------------------------
// Main kernel: warp-per-batch, warps fully independent (NO block-wide sync).
// Weights read directly via LDG (L1-resident). 2048 blocks x 64 threads.
// ---------------------------------------------------------------------------
__global__ __launch_bounds__(64) void fused_kernel(
        const float*    __restrict__ x,      // [B, S, DIN]
        const unsigned* __restrict__ mask,   // [B, S] (bits; !=0 test)
        const float*    __restrict__ W2,     // [HH, 4]
        const float*    __restrict__ b2,     // [4]
        float*          __restrict__ out)    // [B, 2, 4]
{
    // per-warp slab: rows 0..3 speculative + 2 fallback rows
    __shared__ __align__(16) float sxx[2][6][DIN];

    const int warp = threadIdx.x >> 5;
    const int lane = threadIdx.x & 31;
    const int b    = blockIdx.x * 2 + warp;
    const float* xb = x + (size_t)b * SS * DIN;

    // ---- front-batch all independent long-latency loads ----
    const uint4 mv = *reinterpret_cast<const uint4*>(mask + (size_t)b * SS + lane * 4);
    const int pr = lane >> 4;                 // 0/1
    const int pc = (lane & 15) * 4;
    const float4 xa = *reinterpret_cast<const float4*>(xb + (pr + 0) * DIN + pc);
    const float4 xc = *reinterpret_cast<const float4*>(xb + (pr + 2) * DIN + pc);
    const float  bcj = g_bc[lane];
    const float4 w2v = *reinterpret_cast<const float4*>(W2 + lane * 4);
    const float4 b2v = *reinterpret_cast<const float4*>(b2);

    // ---- stage speculative rows 0..3 ----
    *reinterpret_cast<float4*>(&sxx[warp][pr + 0][pc]) = xa;
    *reinterpret_cast<float4*>(&sxx[warp][pr + 2][pc]) = xc;

    // ---- mask scan: first two valid positions ----
    unsigned bits = (mv.x != 0u ? 1u : 0u) | (mv.y != 0u ? 2u : 0u)
                  | (mv.z != 0u ? 4u : 0u) | (mv.w != 0u ? 8u : 0u);
    const unsigned any = __ballot_sync(0xffffffffu, bits != 0u);
    const bool valid = (any != 0u);
    int i0 = 0, i1 = 0;
    if (valid) {
        const int t0 = __ffs(any) - 1;
        const unsigned c0 = __shfl_sync(0xffffffffu, bits, t0);
        i0 = t0 * 4 + (__ffs(c0) - 1);
        const unsigned c0r = c0 & (c0 - 1);
        if (c0r) {
            i1 = t0 * 4 + (__ffs(c0r) - 1);
        } else {
            const unsigned any2 = any & (any - 1);
            if (any2) {
                const int t1 = __ffs(any2) - 1;
                const unsigned c1 = __shfl_sync(0xffffffffu, bits, t1);
                i1 = t1 * 4 + (__ffs(c1) - 1);
            } else {
                i1 = i0;          // nv==1: top2 = preds[:,0]
            }
        }
    }

    // ---- rare fallback gather (~8% of warps) ----
    int s0 = i0, s1 = i1;
    if (i0 >= 4) {                 // warp-uniform
        if (lane < 16)
            *reinterpret_cast<float4*>(&sxx[warp][4][(lane & 15) * 4]) =
                *reinterpret_cast<const float4*>(xb + i0 * DIN + (lane & 15) * 4);
        s0 = 4;
    }
    if (i1 >= 4) {
        if (lane >= 16)
            *reinterpret_cast<float4*>(&sxx[warp][5][(lane & 15) * 4]) =
                *reinterpret_cast<const float4*>(xb + i1 * DIN + (lane & 15) * 4);
        s1 = (i1 == i0) ? 4 : 5;
    }
    __syncwarp();                  // slab visible within the warp only

    // ---- h = relu(x @ Wc + bc): LDS broadcasts + LDG.128 weights (L1-hot) ----
    const float* xr0 = sxx[warp][s0];
    const float* xr1 = sxx[warp][s1];
    const float* wj  = g_WcT + lane * DIN;   // this lane's weight column
    float h0 = bcj, h1 = bcj;
    #pragma unroll
    for (int d = 0; d < DIN; d += 4) {
        const float4 wv = *reinterpret_cast<const float4*>(wj + d);
        const float4 x0 = *reinterpret_cast<const float4*>(xr0 + d);
        const float4 x1 = *reinterpret_cast<const float4*>(xr1 + d);
        h0 = fmaf(x0.x, wv.x, h0); h1 = fmaf(x1.x, wv.x, h1);
        h0 = fmaf(x0.y, wv.y, h0); h1 = fmaf(x1.y, wv.y, h1);
        h0 = fmaf(x0.z, wv.z, h0); h1 = fmaf(x1.z, wv.z, h1);
        h0 = fmaf(x0.w, wv.w, h0); h1 = fmaf(x1.w, wv.w, h1);
    }
    h0 = fmaxf(h0, 0.f);
    h1 = fmaxf(h1, 0.f);

    // ---- preds = h @ W2 (+ b2): 8 warp butterfly reductions ----
    float p[8];
    p[0] = h0 * w2v.x;  p[1] = h0 * w2v.y;  p[2] = h0 * w2v.z;  p[3] = h0 * w2v.w;
    p[4] = h1 * w2v.x;  p[5] = h1 * w2v.y;  p[6] = h1 * w2v.z;  p[7] = h1 * w2v.w;
    #pragma unroll
    for (int i = 0; i < 8; i++) {
        #pragma unroll
        for (int off = 16; off; off >>= 1)
            p[i] += __shfl_xor_sync(0xffffffffu, p[i], off);
    }

    if (lane == 0) {
        float4 o0, o1;
        if (valid) {
            o0 = make_float4(p[0] + b2v.x, p[1] + b2v.y, p[2] + b2v.z, p[3] + b2v.w);
            o1 = make_float4(p[4] + b2v.x, p[5] + b2v.y, p[6] + b2v.z, p[7] + b2v.w);
        } else {
            o0 = make_float4(0.f, 0.f, 0.f, 0.f);
            o1 = o0;
        }
        float4* ob = reinterpret_cast<float4*>(out + (size_t)b * 8);
        ob[0] = o0;
        ob[1] = o1;
    }
}

// ---------------------------------------------------------------------------
// Inputs (metadata order): x, W_net, b_net, W1, b1, W2, b2, mask
// Output: float32 [4096, 2, 4]
// ---------------------------------------------------------------------------
extern "C" void kernel_launch(void* const* d_in, const int* in_sizes, int n_in,
                              void* d_out, int out_size) {
    const float*    x    = (const float*)d_in[0];
    const float*    Wnet = (const float*)d_in[1];
    const float*    bnet = (const float*)d_in[2];
    const float*    W1   = (const float*)d_in[3];
    const float*    b1   = (const float*)d_in[4];
    const float*    W2   = (const float*)d_in[5];
    const float*    b2   = (const float*)d_in[6];
    const unsigned* mask = (const unsigned*)d_in[7];
    float* out = (float*)d_out;

    prep_kernel<<<260, 256>>>(Wnet, bnet, W1, b1);
    fused_kernel<<<BB / 2, 64>>>(x, mask, W2, b2, out);
}

// round 6
// speedup vs baseline: 1.3233x; 1.3233x over previous
#include <cuda_runtime.h>
#include <cuda_bf16.h>

#define BB   4096
#define SS   128
#define DIN  64
#define DOUT 128
#define HH   32
#define WCT_PITCH 68   // 64 + 4 pad: per-lane LDS.128 conflict-free

// Fused first layer, transposed: g_WcT[j][d] = (W_net @ W1)[d][j]; bc = b_net@W1 + b1
__device__ float g_WcT[HH * DIN];
__device__ float g_bc[HH];

// ---------------------------------------------------------------------------
// Prologue: warp-per-element fold (32-way K split + butterfly), 260 x 8 warps.
// Fires the programmatic-launch trigger immediately so the consumer kernel
// ramps concurrently.
// ---------------------------------------------------------------------------
__global__ __launch_bounds__(256) void prep_kernel(
        const float* __restrict__ Wnet, const float* __restrict__ bnet,
        const float* __restrict__ W1,   const float* __restrict__ b1) {
    cudaTriggerProgrammaticLaunchCompletion();

    const int warp = threadIdx.x >> 5;
    const int lane = threadIdx.x & 31;
    const int we   = blockIdx.x * 8 + warp;

    if (we < DIN * HH) {
        const int d = we >> 5, j = we & 31;
        const float4 wn = *reinterpret_cast<const float4*>(Wnet + d * DOUT + lane * 4);
        const int k = lane * 4;
        float acc = wn.x * W1[(k + 0) * HH + j];
        acc = fmaf(wn.y, W1[(k + 1) * HH + j], acc);
        acc = fmaf(wn.z, W1[(k + 2) * HH + j], acc);
        acc = fmaf(wn.w, W1[(k + 3) * HH + j], acc);
        #pragma unroll
        for (int off = 16; off; off >>= 1)
            acc += __shfl_xor_sync(0xffffffffu, acc, off);
        if (lane == 0) g_WcT[j * DIN + d] = acc;
    } else if (we < DIN * HH + HH) {
        const int j = we - DIN * HH;
        const int k = lane * 4;
        float acc = bnet[k + 0] * W1[(k + 0) * HH + j];
        acc = fmaf(bnet[k + 1], W1[(k + 1) * HH + j], acc);
        acc = fmaf(bnet[k + 2], W1[(k + 2) * HH + j], acc);
        acc = fmaf(bnet[k + 3], W1[(k + 3) * HH + j], acc);
        #pragma unroll
        for (int off = 16; off; off >>= 1)
            acc += __shfl_xor_sync(0xffffffffu, acc, off);
        if (lane == 0) g_bc[j] = b1[j] + acc;
    }
}

// ---------------------------------------------------------------------------
// Main kernel (R3 structure): warp-per-batch, 512 blocks x 256 threads.
// All prep-independent work happens BEFORE cudaGridDependencySynchronize().
// ---------------------------------------------------------------------------
__global__ __launch_bounds__(256) void fused_kernel(
        const float*    __restrict__ x,      // [B, S, DIN]
        const unsigned* __restrict__ mask,   // [B, S] (bits; !=0 test)
        const float*    __restrict__ W2,     // [HH, 4]
        const float*    __restrict__ b2,     // [4]
        float*          __restrict__ out)    // [B, 2, 4]
{
    __shared__ __align__(16) float sWcT[HH * WCT_PITCH];       // 8.7 KB
    __shared__ __align__(16) float sxx[8][6][DIN];             // 12 KB

    const int warp = threadIdx.x >> 5;
    const int lane = threadIdx.x & 31;
    const int b    = blockIdx.x * 8 + warp;
    const float* xb = x + (size_t)b * SS * DIN;

    // ---- front-batch all prep-independent long-latency loads ----
    const uint4 mv = *reinterpret_cast<const uint4*>(mask + (size_t)b * SS + lane * 4);
    const int pr = lane >> 4;                 // 0/1
    const int pc = (lane & 15) * 4;
    const float4 xa = *reinterpret_cast<const float4*>(xb + (pr + 0) * DIN + pc);
    const float4 xc = *reinterpret_cast<const float4*>(xb + (pr + 2) * DIN + pc);
    const float4 w2v = *reinterpret_cast<const float4*>(W2 + lane * 4);
    const float4 b2v = *reinterpret_cast<const float4*>(b2);

    // ---- stage speculative rows 0..3 ----
    *reinterpret_cast<float4*>(&sxx[warp][pr + 0][pc]) = xa;
    *reinterpret_cast<float4*>(&sxx[warp][pr + 2][pc]) = xc;

    // ---- mask scan: first two valid positions ----
    unsigned bits = (mv.x != 0u ? 1u : 0u) | (mv.y != 0u ? 2u : 0u)
                  | (mv.z != 0u ? 4u : 0u) | (mv.w != 0u ? 8u : 0u);
    const unsigned any = __ballot_sync(0xffffffffu, bits != 0u);
    const bool valid = (any != 0u);
    int i0 = 0, i1 = 0;
    if (valid) {
        const int t0 = __ffs(any) - 1;
        const unsigned c0 = __shfl_sync(0xffffffffu, bits, t0);
        i0 = t0 * 4 + (__ffs(c0) - 1);
        const unsigned c0r = c0 & (c0 - 1);
        if (c0r) {
            i1 = t0 * 4 + (__ffs(c0r) - 1);
        } else {
            const unsigned any2 = any & (any - 1);
            if (any2) {
                const int t1 = __ffs(any2) - 1;
                const unsigned c1 = __shfl_sync(0xffffffffu, bits, t1);
                i1 = t1 * 4 + (__ffs(c1) - 1);
            } else {
                i1 = i0;          // nv==1: top2 = preds[:,0]
            }
        }
    }

    // ---- rare fallback gather (~8% of warps) ----
    int s0 = i0, s1 = i1;
    if (i0 >= 4) {                 // warp-uniform
        if (lane < 16)
            *reinterpret_cast<float4*>(&sxx[warp][4][(lane & 15) * 4]) =
                *reinterpret_cast<const float4*>(xb + i0 * DIN + (lane & 15) * 4);
        s0 = 4;
    }
    if (i1 >= 4) {
        if (lane >= 16)
            *reinterpret_cast<float4*>(&sxx[warp][5][(lane & 15) * 4]) =
                *reinterpret_cast<const float4*>(xb + i1 * DIN + (lane & 15) * 4);
        s1 = (i1 == i0) ? 4 : 5;
    }

    // ---- wait for prep results, then stage weights ----
    cudaGridDependencySynchronize();

    #pragma unroll
    for (int i = threadIdx.x; i < HH * DIN; i += 256) {
        const int j = i >> 6, d = i & 63;
        sWcT[j * WCT_PITCH + d] = g_WcT[i];
    }
    const float bcj = g_bc[lane];
    __syncthreads();

    // ---- h = relu(x @ Wc + bc): conflict-free LDS.128 ----
    const float* xr0  = sxx[warp][s0];
    const float* xr1  = sxx[warp][s1];
    const float* wrow = sWcT + lane * WCT_PITCH;
    float h0 = bcj, h1 = bcj;
    #pragma unroll
    for (int d = 0; d < DIN; d += 4) {
        const float4 wv = *reinterpret_cast<const float4*>(wrow + d);
        const float4 x0 = *reinterpret_cast<const float4*>(xr0 + d);
        const float4 x1 = *reinterpret_cast<const float4*>(xr1 + d);
        h0 = fmaf(x0.x, wv.x, h0); h1 = fmaf(x1.x, wv.x, h1);
        h0 = fmaf(x0.y, wv.y, h0); h1 = fmaf(x1.y, wv.y, h1);
        h0 = fmaf(x0.z, wv.z, h0); h1 = fmaf(x1.z, wv.z, h1);
        h0 = fmaf(x0.w, wv.w, h0); h1 = fmaf(x1.w, wv.w, h1);
    }
    h0 = fmaxf(h0, 0.f);
    h1 = fmaxf(h1, 0.f);

    // ---- preds = h @ W2 (+ b2): 8 warp butterfly reductions ----
    float p[8];
    p[0] = h0 * w2v.x;  p[1] = h0 * w2v.y;  p[2] = h0 * w2v.z;  p[3] = h0 * w2v.w;
    p[4] = h1 * w2v.x;  p[5] = h1 * w2v.y;  p[6] = h1 * w2v.z;  p[7] = h1 * w2v.w;
    #pragma unroll
    for (int i = 0; i < 8; i++) {
        #pragma unroll
        for (int off = 16; off; off >>= 1)
            p[i] += __shfl_xor_sync(0xffffffffu, p[i], off);
    }

    if (lane == 0) {
        float4 o0, o1;
        if (valid) {
            o0 = make_float4(p[0] + b2v.x, p[1] + b2v.y, p[2] + b2v.z, p[3] + b2v.w);
            o1 = make_float4(p[4] + b2v.x, p[5] + b2v.y, p[6] + b2v.z, p[7] + b2v.w);
        } else {
            o0 = make_float4(0.f, 0.f, 0.f, 0.f);
            o1 = o0;
        }
        float4* ob = reinterpret_cast<float4*>(out + (size_t)b * 8);
        ob[0] = o0;
        ob[1] = o1;
    }
}

// ---------------------------------------------------------------------------
// Inputs (metadata order): x, W_net, b_net, W1, b1, W2, b2, mask
// Output: float32 [4096, 2, 4]
// ---------------------------------------------------------------------------
extern "C" void kernel_launch(void* const* d_in, const int* in_sizes, int n_in,
                              void* d_out, int out_size) {
    const float*    x    = (const float*)d_in[0];
    const float*    Wnet = (const float*)d_in[1];
    const float*    bnet = (const float*)d_in[2];
    const float*    W1   = (const float*)d_in[3];
    const float*    b1   = (const float*)d_in[4];
    const float*    W2   = (const float*)d_in[5];
    const float*    b2   = (const float*)d_in[6];
    const unsigned* mask = (const unsigned*)d_in[7];
    float* out = (float*)d_out;

    // Producer
    prep_kernel<<<260, 256>>>(Wnet, bnet, W1, b1);

    // Consumer with programmatic dependent launch: overlaps its ramp and all
    // prep-independent loads with prep_kernel's execution.
    cudaLaunchConfig_t cfg = {};
    cfg.gridDim  = dim3(512, 1, 1);
    cfg.blockDim = dim3(256, 1, 1);
    cfg.dynamicSmemBytes = 0;
    cfg.stream = 0;   // legacy default stream (same as <<<>>> above)
    cudaLaunchAttribute attr[1];
    attr[0].id = cudaLaunchAttributeProgrammaticStreamSerialization;
    attr[0].val.programmaticStreamSerializationAllowed = 1;
    cfg.attrs = attr;
    cfg.numAttrs = 1;
    cudaLaunchKernelEx(&cfg, fused_kernel, x, mask, W2, b2, out);
}

// round 7
// speedup vs baseline: 1.5394x; 1.1633x over previous
#include <cuda_runtime.h>
#include <cuda_bf16.h>

#define BB   4096
#define SS   128
#define DIN  64
#define DOUT 128
#define HH   32

// Fused first layer, PACKED: g_Wcp[(d>>2)*HH*4 + j*4 + (d&3)] = (W_net@W1)[d][j]
// => lane j at step d4 loads float4 at (d4*HH + j)*4 : warp access = 512B coalesced.
__device__ float g_Wcp[DIN * HH];
__device__ float g_bc[HH];

// ---------------------------------------------------------------------------
// Prologue: warp-per-element fold (32-way K split + butterfly), 260 x 8 warps.
// Triggers programmatic launch completion immediately.
// ---------------------------------------------------------------------------
__global__ __launch_bounds__(256) void prep_kernel(
        const float* __restrict__ Wnet, const float* __restrict__ bnet,
        const float* __restrict__ W1,   const float* __restrict__ b1) {
    cudaTriggerProgrammaticLaunchCompletion();

    const int warp = threadIdx.x >> 5;
    const int lane = threadIdx.x & 31;
    const int we   = blockIdx.x * 8 + warp;

    if (we < DIN * HH) {
        const int d = we >> 5, j = we & 31;
        const float4 wn = *reinterpret_cast<const float4*>(Wnet + d * DOUT + lane * 4);
        const int k = lane * 4;
        float acc = wn.x * W1[(k + 0) * HH + j];
        acc = fmaf(wn.y, W1[(k + 1) * HH + j], acc);
        acc = fmaf(wn.z, W1[(k + 2) * HH + j], acc);
        acc = fmaf(wn.w, W1[(k + 3) * HH + j], acc);
        #pragma unroll
        for (int off = 16; off; off >>= 1)
            acc += __shfl_xor_sync(0xffffffffu, acc, off);
        if (lane == 0)
            g_Wcp[(d >> 2) * (HH * 4) + j * 4 + (d & 3)] = acc;
    } else if (we < DIN * HH + HH) {
        const int j = we - DIN * HH;
        const int k = lane * 4;
        float acc = bnet[k + 0] * W1[(k + 0) * HH + j];
        acc = fmaf(bnet[k + 1], W1[(k + 1) * HH + j], acc);
        acc = fmaf(bnet[k + 2], W1[(k + 2) * HH + j], acc);
        acc = fmaf(bnet[k + 3], W1[(k + 3) * HH + j], acc);
        #pragma unroll
        for (int off = 16; off; off >>= 1)
            acc += __shfl_xor_sync(0xffffffffu, acc, off);
        if (lane == 0) g_bc[j] = b1[j] + acc;
    }
}

// ---------------------------------------------------------------------------
// Main kernel: warp-per-batch, NO block-wide syncs, weights via coalesced
// L1-hot LDG.128. 1024 blocks x 128 threads (4 warps).
// ---------------------------------------------------------------------------
__global__ __launch_bounds__(128, 8) void fused_kernel(
        const float*    __restrict__ x,      // [B, S, DIN]
        const unsigned* __restrict__ mask,   // [B, S] (bits; !=0 test)
        const float*    __restrict__ W2,     // [HH, 4]
        const float*    __restrict__ b2,     // [4]
        float*          __restrict__ out)    // [B, 2, 4]
{
    __shared__ __align__(16) float sxx[4][6][DIN];   // per-warp: 4 spec + 2 fallback

    const int warp = threadIdx.x >> 5;
    const int lane = threadIdx.x & 31;
    const int b    = blockIdx.x * 4 + warp;
    const float* xb = x + (size_t)b * SS * DIN;

    // ---- front-batch all prep-independent long-latency loads ----
    const uint4 mv = *reinterpret_cast<const uint4*>(mask + (size_t)b * SS + lane * 4);
    const int pr = lane >> 4;                 // 0/1
    const int pc = (lane & 15) * 4;
    const float4 xa = *reinterpret_cast<const float4*>(xb + (pr + 0) * DIN + pc);
    const float4 xc = *reinterpret_cast<const float4*>(xb + (pr + 2) * DIN + pc);
    const float4 w2v = *reinterpret_cast<const float4*>(W2 + lane * 4);
    const float4 b2v = *reinterpret_cast<const float4*>(b2);

    // ---- stage speculative rows 0..3 (private warp slab) ----
    *reinterpret_cast<float4*>(&sxx[warp][pr + 0][pc]) = xa;
    *reinterpret_cast<float4*>(&sxx[warp][pr + 2][pc]) = xc;

    // ---- mask scan: first two valid positions ----
    unsigned bits = (mv.x != 0u ? 1u : 0u) | (mv.y != 0u ? 2u : 0u)
                  | (mv.z != 0u ? 4u : 0u) | (mv.w != 0u ? 8u : 0u);
    const unsigned any = __ballot_sync(0xffffffffu, bits != 0u);
    const bool valid = (any != 0u);
    int i0 = 0, i1 = 0;
    if (valid) {
        const int t0 = __ffs(any) - 1;
        const unsigned c0 = __shfl_sync(0xffffffffu, bits, t0);
        i0 = t0 * 4 + (__ffs(c0) - 1);
        const unsigned c0r = c0 & (c0 - 1);
        if (c0r) {
            i1 = t0 * 4 + (__ffs(c0r) - 1);
        } else {
            const unsigned any2 = any & (any - 1);
            if (any2) {
                const int t1 = __ffs(any2) - 1;
                const unsigned c1 = __shfl_sync(0xffffffffu, bits, t1);
                i1 = t1 * 4 + (__ffs(c1) - 1);
            } else {
                i1 = i0;          // nv==1: top2 = preds[:,0]
            }
        }
    }

    // ---- rare fallback gather (~8% of warps), still prep-independent ----
    int s0 = i0, s1 = i1;
    if (i0 >= 4) {                 // warp-uniform
        if (lane < 16)
            *reinterpret_cast<float4*>(&sxx[warp][4][(lane & 15) * 4]) =
                *reinterpret_cast<const float4*>(xb + i0 * DIN + (lane & 15) * 4);
        s0 = 4;
    }
    if (i1 >= 4) {
        if (lane >= 16)
            *reinterpret_cast<float4*>(&sxx[warp][5][(lane & 15) * 4]) =
                *reinterpret_cast<const float4*>(xb + i1 * DIN + (lane & 15) * 4);
        s1 = (i1 == i0) ? 4 : 5;
    }
    __syncwarp();

    // ---- wait for folded weights (prep), then compute ----
    cudaGridDependencySynchronize();

    const float  bcj = g_bc[lane];
    const float* xr0 = sxx[warp][s0];
    const float* xr1 = sxx[warp][s1];
    const float* wp  = g_Wcp + lane * 4;     // this lane's j-column, packed

    float h0 = bcj, h1 = bcj;
    #pragma unroll 4
    for (int d4 = 0; d4 < DIN / 4; d4++) {
        const float4 wv = *reinterpret_cast<const float4*>(wp + d4 * (HH * 4));
        const float4 x0 = *reinterpret_cast<const float4*>(xr0 + d4 * 4);
        const float4 x1 = *reinterpret_cast<const float4*>(xr1 + d4 * 4);
        h0 = fmaf(x0.x, wv.x, h0); h1 = fmaf(x1.x, wv.x, h1);
        h0 = fmaf(x0.y, wv.y, h0); h1 = fmaf(x1.y, wv.y, h1);
        h0 = fmaf(x0.z, wv.z, h0); h1 = fmaf(x1.z, wv.z, h1);
        h0 = fmaf(x0.w, wv.w, h0); h1 = fmaf(x1.w, wv.w, h1);
    }
    h0 = fmaxf(h0, 0.f);
    h1 = fmaxf(h1, 0.f);

    // ---- preds = h @ W2 (+ b2): 8 warp butterfly reductions ----
    float p[8];
    p[0] = h0 * w2v.x;  p[1] = h0 * w2v.y;  p[2] = h0 * w2v.z;  p[3] = h0 * w2v.w;
    p[4] = h1 * w2v.x;  p[5] = h1 * w2v.y;  p[6] = h1 * w2v.z;  p[7] = h1 * w2v.w;
    #pragma unroll
    for (int i = 0; i < 8; i++) {
        #pragma unroll
        for (int off = 16; off; off >>= 1)
            p[i] += __shfl_xor_sync(0xffffffffu, p[i], off);
    }

    if (lane == 0) {
        float4 o0, o1;
        if (valid) {
            o0 = make_float4(p[0] + b2v.x, p[1] + b2v.y, p[2] + b2v.z, p[3] + b2v.w);
            o1 = make_float4(p[4] + b2v.x, p[5] + b2v.y, p[6] + b2v.z, p[7] + b2v.w);
        } else {
            o0 = make_float4(0.f, 0.f, 0.f, 0.f);
            o1 = o0;
        }
        float4* ob = reinterpret_cast<float4*>(out + (size_t)b * 8);
        ob[0] = o0;
        ob[1] = o1;
    }
}

// ---------------------------------------------------------------------------
// Inputs (metadata order): x, W_net, b_net, W1, b1, W2, b2, mask
// Output: float32 [4096, 2, 4]
// ---------------------------------------------------------------------------
extern "C" void kernel_launch(void* const* d_in, const int* in_sizes, int n_in,
                              void* d_out, int out_size) {
    const float*    x    = (const float*)d_in[0];
    const float*    Wnet = (const float*)d_in[1];
    const float*    bnet = (const float*)d_in[2];
    const float*    W1   = (const float*)d_in[3];
    const float*    b1   = (const float*)d_in[4];
    const float*    W2   = (const float*)d_in[5];
    const float*    b2   = (const float*)d_in[6];
    const unsigned* mask = (const unsigned*)d_in[7];
    float* out = (float*)d_out;

    // Producer
    prep_kernel<<<260, 256>>>(Wnet, bnet, W1, b1);

    // Consumer with programmatic dependent launch (overlaps ramp with prep).
    cudaLaunchConfig_t cfg = {};
    cfg.gridDim  = dim3(1024, 1, 1);
    cfg.blockDim = dim3(128, 1, 1);
    cfg.dynamicSmemBytes = 0;
    cfg.stream = 0;   // legacy default stream
    cudaLaunchAttribute attr[1];
    attr[0].id = cudaLaunchAttributeProgrammaticStreamSerialization;
    attr[0].val.programmaticStreamSerializationAllowed = 1;
    cfg.attrs = attr;
    cfg.numAttrs = 1;
    cudaLaunchKernelEx(&cfg, fused_kernel, x, mask, W2, b2, out);
}